// round 8
// baseline (speedup 1.0000x reference)
#include <cuda_runtime.h>

// MultiLayerRNNModel: 2-layer tanh RNN, T=2048, B=4096, I=3, H=5
// out = concat(out[T,B,H], h_n[2,B,H])
//
// R8: intra-warp role split, uniform code path. 16 lanes per batch:
// lanes 0-7 compute layer-0 units, lanes 8-15 layer-1 units (pipelined:
// step t -> h0(t) and h1(t-1)). Both roles run the SAME instruction
// sequence  y = tanh(sum W1.R1 + sum W2.h0v + bias)  with role-dependent
// weights (no divergence; 3 FSELs select R1[0..2] = x vs h1v).
// 2048 warps total (4/SMSP on 128 SMs) vs 1024 before -> the smem comm
// round trip is hidden by 4-way warp interleaving, with ONE __syncwarp
// per step (intra-warp only; R6 showed __syncthreads is fatal).

#define T_LEN   2048
#define B_SZ    4096
#define XSTRIDE (B_SZ * 3)
#define OSTRIDE (B_SZ * 5)

__device__ __forceinline__ float tanh_fast(float v) {
    float y;
    asm("tanh.approx.f32 %0, %1;" : "=f"(y) : "f"(v));
    return y;
}

__global__ __launch_bounds__(512, 1)
void rnn2_kernel(const float* __restrict__ x,
                 const float* __restrict__ hx,
                 const float* __restrict__ w_ih0,
                 const float* __restrict__ w_hh0,
                 const float* __restrict__ b_ih0,
                 const float* __restrict__ b_hh0,
                 const float* __restrict__ w_ih1,
                 const float* __restrict__ w_hh1,
                 const float* __restrict__ b_ih1,
                 const float* __restrict__ b_hh1,
                 float* __restrict__ out)
{
    // 32 batch slots x 16 floats: [0..4]=h0, [8..12]=h1, rest pad.
    // Per warp: 2 slots at 64B spacing -> LDS.128 broadcast, conflict-free.
    __shared__ __align__(16) float buf[2][32][16];

    const int r    = threadIdx.x & 15;
    const int role = r >> 3;                   // 0 = layer0, 1 = layer1
    const int j    = r & 7;                    // unit (active j<5)
    const int slot = threadIdx.x >> 4;         // 0..31
    const int b    = blockIdx.x * 32 + slot;   // exact: 128*32 = 4096
    const bool act = (j < 5);
    const bool l0  = (role == 0);
    const bool st1 = (!l0) && act;             // this lane stores out
    const int  jj  = act ? j : 0;

    // role-dependent weights, uniform step expression:
    //  sum = W1[0..2].R1[0..2] + W1[3..4].h1v[3..4] + W2.h0v + bias
    //  L0: W1 = (wi0, 0, 0), R1 = x(t);  W2 = wh0;  y = h0(t)
    //  L1: W1 = wh1,         R1 = h1v;   W2 = wi1;  y = h1(t-1)
    float W1[5], W2[5], bias;
    if (l0) {
        W1[0] = w_ih0[jj * 3 + 0];
        W1[1] = w_ih0[jj * 3 + 1];
        W1[2] = w_ih0[jj * 3 + 2];
        W1[3] = 0.f; W1[4] = 0.f;
        #pragma unroll
        for (int k = 0; k < 5; k++) W2[k] = w_hh0[jj * 5 + k];
        bias = b_ih0[jj] + b_hh0[jj];
    } else {
        #pragma unroll
        for (int k = 0; k < 5; k++) {
            W1[k] = w_hh1[jj * 5 + k];
            W2[k] = w_ih1[jj * 5 + k];
        }
        bias = b_ih1[jj] + b_hh1[jj];
    }

    // state: at loop head h0x = h0(t-1), h1x = h1(t-2)
    float h00, h01, h02, h03, h04, h10, h11, h12, h13, h14;
    h00 = hx[b * 5 + 0]; h01 = hx[b * 5 + 1]; h02 = hx[b * 5 + 2];
    h03 = hx[b * 5 + 3]; h04 = hx[b * 5 + 4];
    h10 = hx[B_SZ * 5 + b * 5 + 0]; h11 = hx[B_SZ * 5 + b * 5 + 1];
    h12 = hx[B_SZ * 5 + b * 5 + 2]; h13 = hx[B_SZ * 5 + b * 5 + 3];
    h14 = hx[B_SZ * 5 + b * 5 + 4];

    const float* xb   = x + b * 3;
    float*       outp = out + b * 5 + j;
    float* wp = &buf[0][slot][role * 8 + j];   // own write cell
    const float* rp = &buf[0][slot][0];        // slot read base
    const int PAR = 32 * 16;                   // parity stride in floats

    // x queue (L0 lanes only; L1 lanes keep zeros, selected away)
    float xq[8][3];
    #pragma unroll
    for (int p = 0; p < 8; p++) {
        if (l0) {
            const float* xp = xb + p * XSTRIDE;
            xq[p][0] = xp[0]; xq[p][1] = xp[1]; xq[p][2] = xp[2];
        } else {
            xq[p][0] = 0.f; xq[p][1] = 0.f; xq[p][2] = 0.f;
        }
    }

    float yv = 0.f;   // this lane's latest output (h0j or h1j)

// Uniform pre-activation + tanh. R1[0..2] selected by role.
#define CORE(XP, yreg) {                                                      \
    const float r10 = role ? h10 : xq[XP][0];                                 \
    const float r11 = role ? h11 : xq[XP][1];                                 \
    const float r12 = role ? h12 : xq[XP][2];                                 \
    float c1 = fmaf(W1[1], r11, fmaf(W1[0], r10, bias));                      \
    c1 = fmaf(W1[3], h13, fmaf(W1[2], r12, c1));                              \
    float c2 = fmaf(W2[0], h00, W1[4] * h14);                                 \
    c2 = fmaf(W2[1], h01, c2);                                                \
    float c3 = fmaf(W2[3], h03, W2[2] * h02);                                 \
    c3 = fmaf(W2[4], h04, c3);                                                \
    yreg = tanh_fast((c1 + c2) + c3);                                         \
}

#define READBACK(BP) {                                                        \
    const float4 qa = *(const float4*)(rp + (BP) * PAR);                      \
    const float4 qb = *(const float4*)(rp + (BP) * PAR + 8);                  \
    h00 = qa.x; h01 = qa.y; h02 = qa.z; h03 = qa.w;                           \
    h04 = rp[(BP) * PAR + 4];                                                 \
    h10 = qb.x; h11 = qb.y; h12 = qb.z; h13 = qb.w;                           \
    h14 = rp[(BP) * PAR + 12];                                                \
}

// One step t: uniform compute, store own cell, one warpsync, vector readback.
// XP == t&7, BP == t&1 (literals).
#define STEP(t, XP, BP) {                                                     \
    CORE(XP, yv);                                                             \
    if (l0 && (t) + 8 < T_LEN) {                                              \
        const float* xp = xb + ((t) + 8) * XSTRIDE;                           \
        xq[XP][0] = xp[0]; xq[XP][1] = xp[1]; xq[XP][2] = xp[2];              \
    }                                                                         \
    wp[(BP) * PAR] = yv;                                                      \
    if (st1) outp[((t) - 1) * OSTRIDE] = yv;                                  \
    __syncwarp();                                                             \
    READBACK(BP);                                                             \
}

    // ---- prologue t = 0: L0 computes h0(0); L1 republishes h1(-1) ----
    {
        float y0;
        CORE(0, y0);
        const float h1j = (jj == 0) ? h10 : (jj == 1) ? h11 :
                          (jj == 2) ? h12 : (jj == 3) ? h13 : h14;
        yv = l0 ? y0 : h1j;
        if (l0) {
            const float* xp = xb + 8 * XSTRIDE;
            xq[0][0] = xp[0]; xq[0][1] = xp[1]; xq[0][2] = xp[2];
        }
        wp[0] = yv;
        __syncwarp();
        READBACK(0);
    }

    // ---- main loop: t = 1 .. 2040 (t0 = 8m+1) ----
    for (int t0 = 1; t0 < 2041; t0 += 8) {
        STEP(t0 + 0, 1, 1);
        STEP(t0 + 1, 2, 0);
        STEP(t0 + 2, 3, 1);
        STEP(t0 + 3, 4, 0);
        STEP(t0 + 4, 5, 1);
        STEP(t0 + 5, 6, 0);
        STEP(t0 + 6, 7, 1);
        STEP(t0 + 7, 0, 0);
    }
    // ---- tail: t = 2041 .. 2047 (guards compile-time false: no LDG) ----
    STEP(2041, 1, 1);
    STEP(2042, 2, 0);
    STEP(2043, 3, 1);
    STEP(2044, 4, 0);
    STEP(2045, 5, 1);
    STEP(2046, 6, 0);
    STEP(2047, 7, 1);

    // ---- epilogue ----
    // After STEP(2047): h0x = h0(2047), h1x = h1(2046); yv(L0) = h0(2047)_j.
    if (l0 && act)
        outp[(size_t)T_LEN * OSTRIDE] = yv;                // h_n[0]
    {
        float ye;
        CORE(0, ye);                                        // L1: h1(2047)
        if (st1) {
            outp[(T_LEN - 1) * OSTRIDE]           = ye;     // out[2047]
            outp[(size_t)T_LEN * OSTRIDE + OSTRIDE] = ye;   // h_n[1]
        }
    }
#undef STEP
#undef CORE
#undef READBACK
}

extern "C" void kernel_launch(void* const* d_in, const int* in_sizes, int n_in,
                              void* d_out, int out_size)
{
    const float* x     = (const float*)d_in[0];
    const float* hx    = (const float*)d_in[1];
    const float* w_ih0 = (const float*)d_in[2];
    const float* w_hh0 = (const float*)d_in[3];
    const float* b_ih0 = (const float*)d_in[4];
    const float* b_hh0 = (const float*)d_in[5];
    const float* w_ih1 = (const float*)d_in[6];
    const float* w_hh1 = (const float*)d_in[7];
    const float* b_ih1 = (const float*)d_in[8];
    const float* b_hh1 = (const float*)d_in[9];
    float* out = (float*)d_out;

    // 128 blocks x 512 threads = 2048 warps (4/SMSP on 128 SMs);
    // 32 batches per block, 2 per warp. Single wave, no bounds checks.
    rnn2_kernel<<<128, 512>>>(x, hx, w_ih0, w_hh0, b_ih0, b_hh0,
                              w_ih1, w_hh1, b_ih1, b_hh1, out);
}